// round 13
// baseline (speedup 1.0000x reference)
#include <cuda_runtime.h>
#include <cuda_bf16.h>
#include <mma.h>

using namespace nvcuda;

#define B_ 64
#define S_ 48
#define E_ 512
#define H_ 512
#define G_ 2048  /* 4H */
#define NCTA 128

// ---------------- scratch (static device memory; no allocations) ----------------
__device__ __align__(16) float d_G0[2 * S_ * B_ * G_];   // LN(x@Wih0^T), both dirs
__device__ __align__(16) float d_G1[2 * B_ * G_];        // LN(xc@Wih1^T)
__device__ __align__(16) float d_Zb[2 * B_ * G_];        // per-step h@Whh^T
// tf32 hi/lo pairs stored as float
__device__ __align__(16) float d_hhi[2 * B_ * H_], d_hlo[2 * B_ * H_];
__device__ __align__(16) float d_A0hi[S_ * B_ * E_], d_A0lo[S_ * B_ * E_];
__device__ __align__(16) float d_Wih0hi[2 * G_ * E_], d_Wih0lo[2 * G_ * E_];
__device__ __align__(16) float d_Whh0hi[2 * G_ * H_], d_Whh0lo[2 * G_ * H_];
__device__ __align__(16) float d_Wih1hi[2 * G_ * 2 * H_], d_Wih1lo[2 * G_ * 2 * H_];
__device__ __align__(16) float d_Whh1hi[2 * G_ * H_], d_Whh1lo[2 * G_ * H_];
__device__ __align__(16) float d_XChi[B_ * 2 * H_], d_XClo[B_ * 2 * H_];

// grid-barrier state
__device__ unsigned d_bar_count = 0;
__device__ unsigned d_bar_gen = 0;

// ---------------- helpers ----------------
__device__ __forceinline__ float f2tf32(float x) {
    unsigned r;
    asm("cvt.rna.tf32.f32 %0, %1;" : "=r"(r) : "f"(x));
    return __uint_as_float(r);
}

// two-stage fp64 block reduction (<=16 warps); buf needs >=17 doubles
__device__ __forceinline__ double block_reduce_d(double a, double* buf) {
    const int tid = threadIdx.x;
    for (int o = 16; o > 0; o >>= 1)
        a += __shfl_down_sync(0xffffffffu, a, o);
    const int w = tid >> 5, lane = tid & 31;
    const int nw = blockDim.x >> 5;
    if (lane == 0) buf[w] = a;
    __syncthreads();
    if (w == 0) {
        double v = (lane < nw) ? buf[lane] : 0.0;
        for (int o = 8; o > 0; o >>= 1)
            v += __shfl_down_sync(0xffffffffu, v, o);
        if (lane == 0) buf[16] = v;
    }
    __syncthreads();
    return buf[16];
}

__device__ __forceinline__ float sigmoidf_(float x) { return 1.f / (1.f + expf(-x)); }

// CG-style grid barrier: intra-CTA sync, thread0 fence+atomic+tight poll.
__device__ __forceinline__ void grid_barrier() {
    __syncthreads();
    if (threadIdx.x == 0) {
        __threadfence();
        unsigned gen = *((volatile unsigned*)&d_bar_gen);
        unsigned old = atomicAdd(&d_bar_count, 1u);
        if (old == NCTA - 1) {
            d_bar_count = 0;
            __threadfence();
            atomicAdd(&d_bar_gen, 1u);
        } else {
            while (*((volatile unsigned*)&d_bar_gen) == gen) { }
        }
    }
    __syncthreads();
}

// ---------------- fused split kernel (fp32 -> tf32 hi/lo, float4-vectorized) ----------------
__device__ __forceinline__ void split4(float4 v, float4& h, float4& l) {
    h.x = f2tf32(v.x); l.x = f2tf32(v.x - h.x);
    h.y = f2tf32(v.y); l.y = f2tf32(v.y - h.y);
    h.z = f2tf32(v.z); l.z = f2tf32(v.z - h.z);
    h.w = f2tf32(v.w); l.w = f2tf32(v.w - h.w);
}

__global__ void fused_split_kernel(const float* __restrict__ x, float* __restrict__ xhi, float* __restrict__ xlo, int nx,
                                   const float* __restrict__ s0, float* __restrict__ h0, float* __restrict__ l0, int n0,
                                   const float* __restrict__ s1, float* __restrict__ h1, float* __restrict__ l1, int n1,
                                   const float* __restrict__ s2, float* __restrict__ h2, float* __restrict__ l2, int n2,
                                   const float* __restrict__ s3, float* __restrict__ h3, float* __restrict__ l3, int n3) {
    int i = blockIdx.x * blockDim.x + threadIdx.x;  // float4 index
    if (i < nx) {
        int e4 = i % (E_ / 4);
        int r = i / (E_ / 4);
        int s = r / B_;
        int b = r % B_;
        float4 v = *(const float4*)(x + ((size_t)b * S_ + s) * E_ + e4 * 4);
        float4 hv, lv;
        split4(v, hv, lv);
        ((float4*)xhi)[i] = hv;
        ((float4*)xlo)[i] = lv;
        return;
    }
    i -= nx;
    const float* s; float* h; float* l;
    if (i < n0) { s = s0; h = h0; l = l0; }
    else if ((i -= n0) < n1) { s = s1; h = h1; l = l1; }
    else if ((i -= n1) < n2) { s = s2; h = h2; l = l2; }
    else if ((i -= n2) < n3) { s = s3; h = h3; l = l3; }
    else return;
    float4 v = ((const float4*)s)[i], hv, lv;
    split4(v, hv, lv);
    ((float4*)h)[i] = hv;
    ((float4*)l)[i] = lv;
}

// xc[b][k] = concat(h_dir0[b], h_dir1[b]) tf32 hi/lo
__global__ void build_xc_kernel(const float* __restrict__ hhi, const float* __restrict__ hlo,
                                float* __restrict__ xchi, float* __restrict__ xclo) {
    int i = blockIdx.x * blockDim.x + threadIdx.x;
    if (i < B_ * 2 * H_) {
        int k = i % (2 * H_);
        int b = i / (2 * H_);
        int d = k / H_;
        int j = k % H_;
        size_t src = (size_t)(d * B_ + b) * H_ + j;
        xchi[i] = hhi[src];
        xclo[i] = hlo[src];
    }
}

// ---------------- 3-term split-tf32 GEMM (input projections only) ----------------
template <int BM, int BN>
__global__ void __launch_bounds__(256, 1)
gemm3_tf32_kernel(const float* __restrict__ Ahi, const float* __restrict__ Alo,
                  const float* __restrict__ Whi, const float* __restrict__ Wlo,
                  float* __restrict__ C, int M, int N, int K,
                  long aBatch, long wBatch, long cBatch) {
    constexpr int BK = 16;
    constexpr int LDS = BK + 4;
    const int z = blockIdx.z;
    Ahi += (size_t)z * aBatch; Alo += (size_t)z * aBatch;
    Whi += (size_t)z * wBatch; Wlo += (size_t)z * wBatch;
    C += (size_t)z * cBatch;
    const int m0 = blockIdx.y * BM, n0 = blockIdx.x * BN;
    const int tid = threadIdx.x;

    __shared__ __align__(16) float sAh[BM][LDS];
    __shared__ __align__(16) float sAl[BM][LDS];
    __shared__ __align__(16) float sBh[BN][LDS];
    __shared__ __align__(16) float sBl[BN][LDS];

    wmma::fragment<wmma::accumulator, 16, 16, 8, float> accM0[2][2], accM1[2][2], accX[2][2];
#pragma unroll
    for (int i = 0; i < 2; i++)
#pragma unroll
        for (int j = 0; j < 2; j++) {
            wmma::fill_fragment(accM0[i][j], 0.f);
            wmma::fill_fragment(accM1[i][j], 0.f);
            wmma::fill_fragment(accX[i][j], 0.f);
        }

    const int wid = tid >> 5;
    const int wm = wid >> 2;
    const int wn = wid & 3;
    const int Khalf = K >> 1;

    for (int k0 = 0; k0 < K; k0 += BK) {
#pragma unroll
        for (int i = tid; i < BM * (BK / 4); i += 256) {
            int r = i / (BK / 4), q = i % (BK / 4);
            size_t g = (size_t)(m0 + r) * K + k0 + q * 4;
            *(float4*)&sAh[r][q * 4] = *(const float4*)(Ahi + g);
            *(float4*)&sAl[r][q * 4] = *(const float4*)(Alo + g);
        }
#pragma unroll
        for (int i = tid; i < BN * (BK / 4); i += 256) {
            int r = i / (BK / 4), q = i % (BK / 4);
            size_t g = (size_t)(n0 + r) * K + k0 + q * 4;
            *(float4*)&sBh[r][q * 4] = *(const float4*)(Whi + g);
            *(float4*)&sBl[r][q * 4] = *(const float4*)(Wlo + g);
        }
        __syncthreads();
        const bool firstHalf = (k0 < Khalf);
#pragma unroll
        for (int kk = 0; kk < BK; kk += 8) {
            wmma::fragment<wmma::matrix_a, 16, 16, 8, wmma::precision::tf32, wmma::row_major> ah[2], al[2];
            wmma::fragment<wmma::matrix_b, 16, 16, 8, wmma::precision::tf32, wmma::col_major> bh[2], bl[2];
#pragma unroll
            for (int i = 0; i < 2; i++) {
                wmma::load_matrix_sync(ah[i], &sAh[wm * 32 + i * 16][kk], LDS);
                wmma::load_matrix_sync(al[i], &sAl[wm * 32 + i * 16][kk], LDS);
                wmma::load_matrix_sync(bh[i], &sBh[wn * 32 + i * 16][kk], LDS);
                wmma::load_matrix_sync(bl[i], &sBl[wn * 32 + i * 16][kk], LDS);
            }
            if (firstHalf) {
#pragma unroll
                for (int i = 0; i < 2; i++)
#pragma unroll
                    for (int j = 0; j < 2; j++)
                        wmma::mma_sync(accM0[i][j], ah[i], bh[j], accM0[i][j]);
            } else {
#pragma unroll
                for (int i = 0; i < 2; i++)
#pragma unroll
                    for (int j = 0; j < 2; j++)
                        wmma::mma_sync(accM1[i][j], ah[i], bh[j], accM1[i][j]);
            }
#pragma unroll
            for (int i = 0; i < 2; i++)
#pragma unroll
                for (int j = 0; j < 2; j++) {
                    wmma::mma_sync(accX[i][j], ah[i], bl[j], accX[i][j]);
                    wmma::mma_sync(accX[i][j], al[i], bh[j], accX[i][j]);
                }
        }
        __syncthreads();
    }
#pragma unroll
    for (int i = 0; i < 2; i++)
#pragma unroll
        for (int j = 0; j < 2; j++) {
#pragma unroll
            for (int e = 0; e < accM0[i][j].num_elements; e++)
                accM0[i][j].x[e] = (float)(((double)accM0[i][j].x[e] + (double)accM1[i][j].x[e])
                                           + (double)accX[i][j].x[e]);
            wmma::store_matrix_sync(&C[(size_t)(m0 + wm * 32 + i * 16) * N + n0 + wn * 32 + j * 16],
                                    accM0[i][j], N, wmma::mem_row_major);
        }
}

// ---------------- row LayerNorm: fp32 elementwise, fp64 cross-thread reductions ----------------
__global__ void ln_rows_kernel(float* __restrict__ data, const float* __restrict__ gamma,
                               const float* __restrict__ beta, int rowsPerDir) {
    __shared__ double red[20];
    const int width = G_;
    long row = blockIdx.x;
    int d = (int)(row / rowsPerDir);
    float* p = data + row * (long)width;
    const int tid = threadIdx.x;
    float v[8];
    float ps = 0.f;
#pragma unroll
    for (int q = 0; q < 8; q++) {
        v[q] = p[tid + q * 256];
        ps += v[q];
    }
    double s = block_reduce_d((double)ps, red);
    float mu = (float)(s / width);
    float psq = 0.f;
#pragma unroll
    for (int q = 0; q < 8; q++) {
        float dv = v[q] - mu;
        psq = fmaf(dv, dv, psq);
    }
    double sq = block_reduce_d((double)psq, red);
    float rstd = (float)rsqrt(sq / width + 1e-5);
    const float* g = gamma + (size_t)d * width;
    const float* be = beta + (size_t)d * width;
#pragma unroll
    for (int q = 0; q < 8; q++) {
        int j = tid + q * 256;
        p[j] = fmaf((v[q] - mu) * rstd, g[j], be[j]);
    }
}

// ================= persistent scan kernel (512 threads, 2-way K-split) =================
// SMEM (floats):
//   sWh [16 kb][32 n][33 k] = 16896 ; sWl same           (weights, resident)
//   sA  [buf2][half2][hi/lo2][64*33=2112] = 16896        (A staging; also reused as sComb)
//   sGhh/sBhh [2048] ; sGho/sBho [512]
#define SA_TILE 2112
__global__ void __launch_bounds__(512, 1)
scan_kernel(const float* __restrict__ Whh_hi, const float* __restrict__ Whh_lo,
            const float* __restrict__ gih, long gihTime, long gihDir,
            const float* __restrict__ g_hh, const float* __restrict__ b_hh,
            const float* __restrict__ g_ho, const float* __restrict__ b_ho,
            float* __restrict__ Z, float* __restrict__ hhi, float* __restrict__ hlo,
            int writeOut, float* __restrict__ out) {
    extern __shared__ float sm[];
    float* sWh = sm;                          // 16896
    float* sWl = sWh + 16896;                 // 16896
    float* sA = sWl + 16896;                  // 16896 (staging + combine scratch)
    float* sGhh = sA + 16896;                 // 2048
    float* sBhh = sGhh + 2048;                // 2048
    float* sGho = sBhh + 2048;                // 512
    float* sBho = sGho + 512;                 // 512
    __shared__ double red[20];

    const int tid = threadIdx.x;
    const int cta = blockIdx.x;
    const int d = cta >> 6;                   // direction
    const int n0 = (cta & 63) * 32;           // gemm column block
    const int cb = cta & 63;                  // cell batch row
    const int wid = tid >> 5;
    const int lane = tid & 31;
    const int tile = wid & 7;                 // 0..7: (wm, wn)
    const int kh = wid >> 3;                  // 0..1: K-half
    const int wm = tile >> 1;                 // 0..3 (16-row m slice)
    const int wn = tile & 1;                  // 0..1 (16-col n slice)

    // ---- one-time fills ----
    {
        const float* wh = Whh_hi + ((size_t)d * G_ + n0) * H_;
        const float* wl = Whh_lo + ((size_t)d * G_ + n0) * H_;
        for (int i = tid; i < 32 * H_; i += 512) {
            int r = i >> 9, k = i & 511;
            int kb = k >> 5, kk = k & 31;
            int off = kb * (32 * 33) + r * 33 + kk;
            sWh[off] = __ldg(wh + (size_t)r * H_ + k);
            sWl[off] = __ldg(wl + (size_t)r * H_ + k);
        }
    }
    for (int i = tid; i < G_; i += 512) {
        sGhh[i] = __ldg(g_hh + (size_t)d * G_ + i);
        sBhh[i] = __ldg(b_hh + (size_t)d * G_ + i);
    }
    if (tid < H_) {
        sGho[tid] = __ldg(g_ho + (size_t)d * H_ + tid);
        sBho[tid] = __ldg(b_ho + (size_t)d * H_ + tid);
    }
    if (tid < H_) {
        hhi[(size_t)cta * H_ + tid] = 0.f;
        hlo[(size_t)cta * H_ + tid] = 0.f;
    }
    double c_reg = 0.0;                       // persistent fp64 cell state (1/thread)
    grid_barrier();

    // A staging mapping: thread -> (row r, col group c4) of a 64x32 tile
    const int r_ = tid >> 3;                  // 0..63
    const int c4 = (tid & 7) * 4;             // 0,4,...,28
    const size_t hrow = (size_t)(d * B_ + r_) * H_ + c4;

    for (int t = 0; t < S_; t++) {
        // prefetch gi for cell phase
        const int tt = (d == 0) ? t : (S_ - 1 - t);
        const float* gi = gih + (size_t)d * gihDir + (size_t)tt * gihTime + (size_t)cb * G_;
        float gir[4];
#pragma unroll
        for (int q = 0; q < 4; q++) gir[q] = __ldg(gi + tid + q * 512);

        // ======== GEMM phase (each warp: 16x16 tile, K-half kh) ========
        wmma::fragment<wmma::accumulator, 16, 16, 8, float> accM, accX;
        wmma::fill_fragment(accM, 0.f);
        wmma::fill_fragment(accX, 0.f);

        // prefetch kb=0 tiles for both halves (tiles 0 and 8)
        float4 ph0 = __ldcg((const float4*)(hhi + hrow));
        float4 pl0 = __ldcg((const float4*)(hlo + hrow));
        float4 ph1 = __ldcg((const float4*)(hhi + hrow + 8 * 32));
        float4 pl1 = __ldcg((const float4*)(hlo + hrow + 8 * 32));

#pragma unroll 2
        for (int kb = 0; kb < 8; kb++) {
            const int fb = kb & 1;
            {
                float* d00 = sA + ((fb * 2 + 0) * 2 + 0) * SA_TILE + r_ * 33 + c4;
                float* d01 = sA + ((fb * 2 + 0) * 2 + 1) * SA_TILE + r_ * 33 + c4;
                float* d10 = sA + ((fb * 2 + 1) * 2 + 0) * SA_TILE + r_ * 33 + c4;
                float* d11 = sA + ((fb * 2 + 1) * 2 + 1) * SA_TILE + r_ * 33 + c4;
                d00[0] = ph0.x; d00[1] = ph0.y; d00[2] = ph0.z; d00[3] = ph0.w;
                d01[0] = pl0.x; d01[1] = pl0.y; d01[2] = pl0.z; d01[3] = pl0.w;
                d10[0] = ph1.x; d10[1] = ph1.y; d10[2] = ph1.z; d10[3] = ph1.w;
                d11[0] = pl1.x; d11[1] = pl1.y; d11[2] = pl1.z; d11[3] = pl1.w;
            }
            __syncthreads();
            if (kb < 7) {
                int k0n = (kb + 1) * 32;
                ph0 = __ldcg((const float4*)(hhi + hrow + k0n));
                pl0 = __ldcg((const float4*)(hlo + hrow + k0n));
                ph1 = __ldcg((const float4*)(hhi + hrow + k0n + 8 * 32));
                pl1 = __ldcg((const float4*)(hlo + hrow + k0n + 8 * 32));
            }
            const int kbg = kb + kh * 8;
            const float* bAh = sA + ((fb * 2 + kh) * 2 + 0) * SA_TILE + (wm * 16) * 33;
            const float* bAl = bAh + SA_TILE;
            const float* bWh = sWh + kbg * (32 * 33) + (wn * 16) * 33;
            const float* bWl = sWl + kbg * (32 * 33) + (wn * 16) * 33;
#pragma unroll
            for (int kk = 0; kk < 32; kk += 8) {
                wmma::fragment<wmma::matrix_a, 16, 16, 8, wmma::precision::tf32, wmma::row_major> ah, al;
                wmma::fragment<wmma::matrix_b, 16, 16, 8, wmma::precision::tf32, wmma::col_major> bh, bl;
                wmma::load_matrix_sync(ah, bAh + kk, 33);
                wmma::load_matrix_sync(al, bAl + kk, 33);
                wmma::load_matrix_sync(bh, bWh + kk, 33);
                wmma::load_matrix_sync(bl, bWl + kk, 33);
                wmma::mma_sync(accM, ah, bh, accM);
                wmma::mma_sync(accX, ah, bl, accX);
                wmma::mma_sync(accX, al, bh, accX);
            }
        }
        __syncthreads();   // staging dead; safe to reuse sA as combine scratch
        // K-half combine: kh=1 stores partials, kh=0 combines in fp64 and writes Z
        if (kh == 1) {
            float* pc = sA + (tile * 32 + lane) * 17;
#pragma unroll
            for (int e = 0; e < 8; e++) { pc[e] = accM.x[e]; pc[8 + e] = accX.x[e]; }
        }
        __syncthreads();
        if (kh == 0) {
            const float* pc = sA + (tile * 32 + lane) * 17;
#pragma unroll
            for (int e = 0; e < 8; e++)
                accM.x[e] = (float)(((double)accM.x[e] + (double)pc[e])
                                    + ((double)accX.x[e] + (double)pc[8 + e]));
            wmma::store_matrix_sync(Z + (size_t)(d * B_ + wm * 16) * G_ + n0 + wn * 16,
                                    accM, G_, wmma::mem_row_major);
        }

        grid_barrier();

        // ======== cell phase (row cta = (d, cb)); 1 elem/gate/thread ========
        {
            const float* z = Z + (size_t)cta * G_;
            float zr[4];
            float ps = 0.f;
#pragma unroll
            for (int q = 0; q < 4; q++) {
                zr[q] = __ldcg(z + tid + q * 512);
                ps += zr[q];
            }
            double s = block_reduce_d((double)ps, red);
            float mu = (float)(s / G_);
            float psq = 0.f;
#pragma unroll
            for (int q = 0; q < 4; q++) {
                float dv = zr[q] - mu;
                psq = fmaf(dv, dv, psq);
            }
            double sq = block_reduce_d((double)psq, red);
            float rstd = (float)rsqrt(sq / G_ + 1e-5);

            const int j = tid;
            float ai = fmaf((zr[0] - mu) * rstd, sGhh[j],            sBhh[j])            + gir[0];
            float af = fmaf((zr[1] - mu) * rstd, sGhh[j + H_],       sBhh[j + H_])       + gir[1];
            float ao = fmaf((zr[2] - mu) * rstd, sGhh[j + 2 * H_],   sBhh[j + 2 * H_])   + gir[2];
            float ag = fmaf((zr[3] - mu) * rstd, sGhh[j + 3 * H_],   sBhh[j + 3 * H_])   + gir[3];
            float ig = sigmoidf_(ai);
            float fg = sigmoidf_(af);
            float og = sigmoidf_(ao);
            float gg = tanhf(ag);
            double cn = (double)fg * c_reg + (double)(ig * gg);
            c_reg = cn;

            double s2 = block_reduce_d(cn, red);
            double muc = s2 / H_;
            double dvc = cn - muc;
            double sq2 = block_reduce_d(dvc * dvc, red);
            float rstdc = (float)rsqrt(sq2 / H_ + 1e-5);

            float lnc = fmaf((float)dvc * rstdc, sGho[j], sBho[j]);
            float hn = og * tanhf(lnc);
            size_t hi_ = (size_t)cta * H_ + j;
            float hb = f2tf32(hn);
            hhi[hi_] = hb;
            hlo[hi_] = f2tf32(hn - hb);
            if (writeOut && t == S_ - 1)
                out[(size_t)cb * (2 * H_) + (size_t)d * H_ + j] = hn;
        }
        grid_barrier();
    }
}

// ---------------- host orchestration ----------------
extern "C" void kernel_launch(void* const* d_in, const int* in_sizes, int n_in,
                              void* d_out, int out_size) {
    const float* x = (const float*)d_in[0];
    // d_in[1] = text_length (unused)
    const float* w_ih0 = (const float*)d_in[2];
    const float* w_hh0 = (const float*)d_in[3];
    const float* ln_ih0_g = (const float*)d_in[4];
    const float* ln_ih0_b = (const float*)d_in[5];
    const float* ln_hh0_g = (const float*)d_in[6];
    const float* ln_hh0_b = (const float*)d_in[7];
    const float* ln_ho0_g = (const float*)d_in[8];
    const float* ln_ho0_b = (const float*)d_in[9];
    const float* w_ih1 = (const float*)d_in[10];
    const float* w_hh1 = (const float*)d_in[11];
    const float* ln_ih1_g = (const float*)d_in[12];
    const float* ln_ih1_b = (const float*)d_in[13];
    const float* ln_hh1_g = (const float*)d_in[14];
    const float* ln_hh1_b = (const float*)d_in[15];
    const float* ln_ho1_g = (const float*)d_in[16];
    const float* ln_ho1_b = (const float*)d_in[17];
    float* out = (float*)d_out;

    float *G0, *G1, *Z;
    float *hhi, *hlo, *A0hi, *A0lo, *Wih0hi, *Wih0lo, *Whh0hi, *Whh0lo;
    float *Wih1hi, *Wih1lo, *Whh1hi, *Whh1lo, *XChi, *XClo;
    cudaGetSymbolAddress((void**)&G0, d_G0);
    cudaGetSymbolAddress((void**)&G1, d_G1);
    cudaGetSymbolAddress((void**)&Z, d_Zb);
    cudaGetSymbolAddress((void**)&hhi, d_hhi);
    cudaGetSymbolAddress((void**)&hlo, d_hlo);
    cudaGetSymbolAddress((void**)&A0hi, d_A0hi);
    cudaGetSymbolAddress((void**)&A0lo, d_A0lo);
    cudaGetSymbolAddress((void**)&Wih0hi, d_Wih0hi);
    cudaGetSymbolAddress((void**)&Wih0lo, d_Wih0lo);
    cudaGetSymbolAddress((void**)&Whh0hi, d_Whh0hi);
    cudaGetSymbolAddress((void**)&Whh0lo, d_Whh0lo);
    cudaGetSymbolAddress((void**)&Wih1hi, d_Wih1hi);
    cudaGetSymbolAddress((void**)&Wih1lo, d_Wih1lo);
    cudaGetSymbolAddress((void**)&Whh1hi, d_Whh1hi);
    cudaGetSymbolAddress((void**)&Whh1lo, d_Whh1lo);
    cudaGetSymbolAddress((void**)&XChi, d_XChi);
    cudaGetSymbolAddress((void**)&XClo, d_XClo);

    const int SCAN_SMEM = (16896 * 3 + 2048 * 2 + 512 * 2) * 4;  // 223232 B
    static int attr_set = 0;
    if (!attr_set) {
        cudaFuncSetAttribute(scan_kernel, cudaFuncAttributeMaxDynamicSharedMemorySize, SCAN_SMEM);
        attr_set = 1;
    }

    // 1) fused splits
    {
        int nx = S_ * B_ * E_ / 4;
        int n0 = 2 * G_ * E_ / 4, n1 = 2 * G_ * H_ / 4, n2 = 2 * G_ * 2 * H_ / 4, n3 = 2 * G_ * H_ / 4;
        int total = nx + n0 + n1 + n2 + n3;
        fused_split_kernel<<<(total + 255) / 256, 256>>>(
            x, A0hi, A0lo, nx,
            w_ih0, Wih0hi, Wih0lo, n0,
            w_hh0, Whh0hi, Whh0lo, n1,
            w_ih1, Wih1hi, Wih1lo, n2,
            w_hh1, Whh1hi, Whh1lo, n3);
    }

    // 2) layer-0 input projection
    {
        dim3 grid(G_ / 128, (S_ * B_) / 64, 2);
        gemm3_tf32_kernel<64, 128><<<grid, 256>>>(A0hi, A0lo, Wih0hi, Wih0lo, G0,
                                                  S_ * B_, G_, E_,
                                                  0L, (long)G_ * E_, (long)S_ * B_ * G_);
    }
    // 3) LN
    ln_rows_kernel<<<2 * S_ * B_, 256>>>(G0, ln_ih0_g, ln_ih0_b, S_ * B_);

    // 4) layer-0 persistent scan
    scan_kernel<<<NCTA, 512, SCAN_SMEM>>>(Whh0hi, Whh0lo,
                                          G0, (long)B_ * G_, (long)S_ * B_ * G_,
                                          ln_hh0_g, ln_hh0_b, ln_ho0_g, ln_ho0_b,
                                          Z, hhi, hlo, 0, out);

    // 5) layer-1 input (constant over time due to aliasing bug)
    build_xc_kernel<<<(B_ * 2 * H_ + 255) / 256, 256>>>(hhi, hlo, XChi, XClo);
    {
        dim3 grid(G_ / 128, 1, 2);
        gemm3_tf32_kernel<64, 128><<<grid, 256>>>(XChi, XClo, Wih1hi, Wih1lo, G1,
                                                  B_, G_, 2 * H_,
                                                  0L, (long)G_ * 2 * H_, (long)B_ * G_);
    }
    ln_rows_kernel<<<2 * B_, 256>>>(G1, ln_ih1_g, ln_ih1_b, B_);

    // 6) layer-1 persistent scan
    scan_kernel<<<NCTA, 512, SCAN_SMEM>>>(Whh1hi, Whh1lo,
                                          G1, 0L, (long)B_ * G_,
                                          ln_hh1_g, ln_hh1_b, ln_ho1_g, ln_ho1_b,
                                          Z, hhi, hlo, 1, out);
}

// round 15
// speedup vs baseline: 1.1319x; 1.1319x over previous
#include <cuda_runtime.h>
#include <cuda_fp16.h>
#include <cuda_bf16.h>
#include <mma.h>

using namespace nvcuda;

#define B_ 64
#define S_ 48
#define E_ 512
#define H_ 512
#define G_ 2048  /* 4H */
#define NCTA 128
#define LDSH 56            /* half stride: 112B rows, 16B aligned, LDSM conflict-free */
#define SA_TILE (64 * LDSH)

typedef __half half_t;

// ---------------- scratch (static device memory; no allocations) ----------------
__device__ __align__(16) float d_G0[2 * S_ * B_ * G_];   // LN(x@Wih0^T), both dirs
__device__ __align__(16) float d_G1[2 * B_ * G_];        // LN(xc@Wih1^T)
__device__ __align__(16) float d_Zb[2 * B_ * G_];        // per-step h@Whh^T
// fp16 hi/lo pairs (lo pre-scaled by 2^11)
__device__ __align__(16) half_t d_hhi[2 * B_ * H_], d_hlo[2 * B_ * H_];
__device__ __align__(16) half_t d_A0hi[S_ * B_ * E_], d_A0lo[S_ * B_ * E_];
__device__ __align__(16) half_t d_Wih0hi[2 * G_ * E_], d_Wih0lo[2 * G_ * E_];
__device__ __align__(16) half_t d_Whh0hi[2 * G_ * H_], d_Whh0lo[2 * G_ * H_];
__device__ __align__(16) half_t d_Wih1hi[2 * G_ * 2 * H_], d_Wih1lo[2 * G_ * 2 * H_];
__device__ __align__(16) half_t d_Whh1hi[2 * G_ * H_], d_Whh1lo[2 * G_ * H_];
__device__ __align__(16) half_t d_XChi[B_ * 2 * H_], d_XClo[B_ * 2 * H_];

// grid-barrier state
__device__ unsigned d_bar_count = 0;
__device__ unsigned d_bar_gen = 0;

#define LO_SCALE 2048.0f
#define LO_INV (1.0 / 2048.0)

// ---------------- helpers ----------------
__device__ __forceinline__ double block_reduce_d(double a, double* buf) {
    const int tid = threadIdx.x;
    for (int o = 16; o > 0; o >>= 1)
        a += __shfl_down_sync(0xffffffffu, a, o);
    const int w = tid >> 5, lane = tid & 31;
    const int nw = blockDim.x >> 5;
    if (lane == 0) buf[w] = a;
    __syncthreads();
    if (w == 0) {
        double v = (lane < nw) ? buf[lane] : 0.0;
        for (int o = 8; o > 0; o >>= 1)
            v += __shfl_down_sync(0xffffffffu, v, o);
        if (lane == 0) buf[16] = v;
    }
    __syncthreads();
    return buf[16];
}

__device__ __forceinline__ float sigmoidf_(float x) { return 1.f / (1.f + expf(-x)); }

__device__ __forceinline__ void grid_barrier() {
    __syncthreads();
    if (threadIdx.x == 0) {
        __threadfence();
        unsigned gen = *((volatile unsigned*)&d_bar_gen);
        unsigned old = atomicAdd(&d_bar_count, 1u);
        if (old == NCTA - 1) {
            d_bar_count = 0;
            __threadfence();
            atomicAdd(&d_bar_gen, 1u);
        } else {
            while (*((volatile unsigned*)&d_bar_gen) == gen) { }
        }
    }
    __syncthreads();
}

// ---------------- fp16 hi/lo split (lo scaled by 2^11) ----------------
__device__ __forceinline__ unsigned pack2(__half a, __half b) {
    __half2 t = __halves2half2(a, b);
    return *reinterpret_cast<unsigned*>(&t);
}

__device__ __forceinline__ void split4h(float4 v, uint2& h, uint2& l) {
    __half hx = __float2half_rn(v.x), hy = __float2half_rn(v.y);
    __half hz = __float2half_rn(v.z), hw = __float2half_rn(v.w);
    __half lx = __float2half_rn((v.x - __half2float(hx)) * LO_SCALE);
    __half ly = __float2half_rn((v.y - __half2float(hy)) * LO_SCALE);
    __half lz = __float2half_rn((v.z - __half2float(hz)) * LO_SCALE);
    __half lw = __float2half_rn((v.w - __half2float(hw)) * LO_SCALE);
    h.x = pack2(hx, hy); h.y = pack2(hz, hw);
    l.x = pack2(lx, ly); l.y = pack2(lz, lw);
}

// fused split: x transpose-split + 4 weight splits (sizes in float4 units)
__global__ void fused_split_kernel(const float* __restrict__ x, half_t* __restrict__ xhi, half_t* __restrict__ xlo, int nx,
                                   const float* __restrict__ s0, half_t* __restrict__ h0, half_t* __restrict__ l0, int n0,
                                   const float* __restrict__ s1, half_t* __restrict__ h1, half_t* __restrict__ l1, int n1,
                                   const float* __restrict__ s2, half_t* __restrict__ h2, half_t* __restrict__ l2, int n2,
                                   const float* __restrict__ s3, half_t* __restrict__ h3, half_t* __restrict__ l3, int n3) {
    int i = blockIdx.x * blockDim.x + threadIdx.x;  // float4 index
    if (i < nx) {
        int e4 = i % (E_ / 4);
        int r = i / (E_ / 4);
        int s = r / B_;
        int b = r % B_;
        float4 v = *(const float4*)(x + ((size_t)b * S_ + s) * E_ + e4 * 4);
        uint2 hv, lv;
        split4h(v, hv, lv);
        ((uint2*)xhi)[i] = hv;
        ((uint2*)xlo)[i] = lv;
        return;
    }
    i -= nx;
    const float* s; half_t* h; half_t* l;
    if (i < n0) { s = s0; h = h0; l = l0; }
    else if ((i -= n0) < n1) { s = s1; h = h1; l = l1; }
    else if ((i -= n1) < n2) { s = s2; h = h2; l = l2; }
    else if ((i -= n2) < n3) { s = s3; h = h3; l = l3; }
    else return;
    float4 v = ((const float4*)s)[i];
    uint2 hv, lv;
    split4h(v, hv, lv);
    ((uint2*)h)[i] = hv;
    ((uint2*)l)[i] = lv;
}

// xc[b][k] = concat(h_dir0[b], h_dir1[b]) fp16 hi/lo
__global__ void build_xc_kernel(const half_t* __restrict__ hhi, const half_t* __restrict__ hlo,
                                half_t* __restrict__ xchi, half_t* __restrict__ xclo) {
    int i = blockIdx.x * blockDim.x + threadIdx.x;
    if (i < B_ * 2 * H_) {
        int k = i % (2 * H_);
        int b = i / (2 * H_);
        int d = k / H_;
        int j = k % H_;
        size_t src = (size_t)(d * B_ + b) * H_ + j;
        xchi[i] = hhi[src];
        xclo[i] = hlo[src];
    }
}

// ---------------- 3-term split-fp16 GEMM (input projections) ----------------
// C = Ahi*Whi + (Ahi*Wlo' + Alo'*Whi) * 2^-11 ; main split in two K-halves; fp64 combine
__global__ void __launch_bounds__(256, 1)
gemm3_fp16_kernel(const half_t* __restrict__ Ahi, const half_t* __restrict__ Alo,
                  const half_t* __restrict__ Whi, const half_t* __restrict__ Wlo,
                  float* __restrict__ C, int M, int N, int K,
                  long aBatch, long wBatch, long cBatch) {
    constexpr int BM = 64, BN = 128, BK = 32;
    const int z = blockIdx.z;
    Ahi += (size_t)z * aBatch; Alo += (size_t)z * aBatch;
    Whi += (size_t)z * wBatch; Wlo += (size_t)z * wBatch;
    C += (size_t)z * cBatch;
    const int m0 = blockIdx.y * BM, n0 = blockIdx.x * BN;
    const int tid = threadIdx.x;

    __shared__ __align__(16) half_t sAh[BM][LDSH];
    __shared__ __align__(16) half_t sAl[BM][LDSH];
    __shared__ __align__(16) half_t sBh[BN][LDSH];
    __shared__ __align__(16) half_t sBl[BN][LDSH];

    wmma::fragment<wmma::accumulator, 16, 16, 16, float> accM0[2][2], accM1[2][2], accX[2][2];
#pragma unroll
    for (int i = 0; i < 2; i++)
#pragma unroll
        for (int j = 0; j < 2; j++) {
            wmma::fill_fragment(accM0[i][j], 0.f);
            wmma::fill_fragment(accM1[i][j], 0.f);
            wmma::fill_fragment(accX[i][j], 0.f);
        }

    const int wid = tid >> 5;
    const int wm = wid >> 2;   // 0..1
    const int wn = wid & 3;    // 0..3
    const int Khalf = K >> 1;

    for (int k0 = 0; k0 < K; k0 += BK) {
        // stage A: 64 rows x 32 halves = 256 uint4 ; B: 128 rows = 512 uint4
#pragma unroll
        for (int i = tid; i < BM * 4; i += 256) {
            int r = i >> 2, q = i & 3;
            size_t g = (size_t)(m0 + r) * K + k0 + q * 8;
            *(uint4*)&sAh[r][q * 8] = *(const uint4*)(Ahi + g);
            *(uint4*)&sAl[r][q * 8] = *(const uint4*)(Alo + g);
        }
#pragma unroll
        for (int i = tid; i < BN * 4; i += 256) {
            int r = i >> 2, q = i & 3;
            size_t g = (size_t)(n0 + r) * K + k0 + q * 8;
            *(uint4*)&sBh[r][q * 8] = *(const uint4*)(Whi + g);
            *(uint4*)&sBl[r][q * 8] = *(const uint4*)(Wlo + g);
        }
        __syncthreads();
        const bool firstHalf = (k0 < Khalf);
#pragma unroll
        for (int kk = 0; kk < BK; kk += 16) {
            wmma::fragment<wmma::matrix_a, 16, 16, 16, __half, wmma::row_major> ah[2], al[2];
            wmma::fragment<wmma::matrix_b, 16, 16, 16, __half, wmma::col_major> bh[2], bl[2];
#pragma unroll
            for (int i = 0; i < 2; i++) {
                wmma::load_matrix_sync(ah[i], &sAh[wm * 32 + i * 16][kk], LDSH);
                wmma::load_matrix_sync(al[i], &sAl[wm * 32 + i * 16][kk], LDSH);
                wmma::load_matrix_sync(bh[i], &sBh[wn * 32 + i * 16][kk], LDSH);
                wmma::load_matrix_sync(bl[i], &sBl[wn * 32 + i * 16][kk], LDSH);
            }
            if (firstHalf) {
#pragma unroll
                for (int i = 0; i < 2; i++)
#pragma unroll
                    for (int j = 0; j < 2; j++)
                        wmma::mma_sync(accM0[i][j], ah[i], bh[j], accM0[i][j]);
            } else {
#pragma unroll
                for (int i = 0; i < 2; i++)
#pragma unroll
                    for (int j = 0; j < 2; j++)
                        wmma::mma_sync(accM1[i][j], ah[i], bh[j], accM1[i][j]);
            }
#pragma unroll
            for (int i = 0; i < 2; i++)
#pragma unroll
                for (int j = 0; j < 2; j++) {
                    wmma::mma_sync(accX[i][j], ah[i], bl[j], accX[i][j]);
                    wmma::mma_sync(accX[i][j], al[i], bh[j], accX[i][j]);
                }
        }
        __syncthreads();
    }
#pragma unroll
    for (int i = 0; i < 2; i++)
#pragma unroll
        for (int j = 0; j < 2; j++) {
#pragma unroll
            for (int e = 0; e < accM0[i][j].num_elements; e++)
                accM0[i][j].x[e] = (float)(((double)accM0[i][j].x[e] + (double)accM1[i][j].x[e])
                                           + (double)accX[i][j].x[e] * LO_INV);
            wmma::store_matrix_sync(&C[(size_t)(m0 + wm * 32 + i * 16) * N + n0 + wn * 32 + j * 16],
                                    accM0[i][j], N, wmma::mem_row_major);
        }
}

// ---------------- row LayerNorm: fp32 elementwise, fp64 cross-thread reductions ----------------
__global__ void ln_rows_kernel(float* __restrict__ data, const float* __restrict__ gamma,
                               const float* __restrict__ beta, int rowsPerDir) {
    __shared__ double red[20];
    const int width = G_;
    long row = blockIdx.x;
    int d = (int)(row / rowsPerDir);
    float* p = data + row * (long)width;
    const int tid = threadIdx.x;
    float v[8];
    float ps = 0.f;
#pragma unroll
    for (int q = 0; q < 8; q++) {
        v[q] = p[tid + q * 256];
        ps += v[q];
    }
    double s = block_reduce_d((double)ps, red);
    float mu = (float)(s / width);
    float psq = 0.f;
#pragma unroll
    for (int q = 0; q < 8; q++) {
        float dv = v[q] - mu;
        psq = fmaf(dv, dv, psq);
    }
    double sq = block_reduce_d((double)psq, red);
    float rstd = (float)rsqrt(sq / width + 1e-5);
    const float* g = gamma + (size_t)d * width;
    const float* be = beta + (size_t)d * width;
#pragma unroll
    for (int q = 0; q < 8; q++) {
        int j = tid + q * 256;
        p[j] = fmaf((v[q] - mu) * rstd, g[j], be[j]);
    }
}

// ================= persistent scan kernel (512 threads, fp16 3-term, 2-way K-split) =================
// SMEM halves: sWh[16][32][56]=28672, sWl=28672, sA[2buf][2kh][2part][64][56]=28672
// then floats: sGhh[2048], sBhh[2048], sGho[512], sBho[512]
__global__ void __launch_bounds__(512, 1)
scan_kernel(const half_t* __restrict__ Whh_hi, const half_t* __restrict__ Whh_lo,
            const float* __restrict__ gih, long gihTime, long gihDir,
            const float* __restrict__ g_hh, const float* __restrict__ b_hh,
            const float* __restrict__ g_ho, const float* __restrict__ b_ho,
            float* __restrict__ Z, half_t* __restrict__ hhi, half_t* __restrict__ hlo,
            int writeOut, float* __restrict__ out) {
    extern __shared__ half_t smh[];
    half_t* sWh = smh;                         // 28672 halves
    half_t* sWl = sWh + 28672;                 // 28672
    half_t* sA  = sWl + 28672;                 // 28672 (8 tiles of 3584)
    float* sGhh = (float*)(sA + 28672);        // 2048 floats
    float* sBhh = sGhh + 2048;
    float* sGho = sBhh + 2048;
    float* sBho = sGho + 512;
    float* sComb = (float*)sA;                 // reuse staging as combine scratch
    __shared__ double red[20];

    const int tid = threadIdx.x;
    const int cta = blockIdx.x;
    const int d = cta >> 6;                    // direction
    const int n0 = (cta & 63) * 32;            // gemm column block
    const int cb = cta & 63;                   // cell batch row
    const int wid = tid >> 5;
    const int lane = tid & 31;
    const int wt = wid & 7;                    // warp tile id
    const int kh = wid >> 3;                   // 0..1 K-half
    const int wm = wt >> 1;                    // 0..3 (16-row m slice)
    const int wn = wt & 1;                     // 0..1 (16-col n slice)

    // ---- one-time fills ----
    {
        const half_t* wh = Whh_hi + ((size_t)d * G_ + n0) * H_;
        const half_t* wl = Whh_lo + ((size_t)d * G_ + n0) * H_;
        for (int i = tid; i < 32 * H_; i += 512) {
            int r = i >> 9, k = i & 511;
            int kb = k >> 5, kk = k & 31;
            int off = kb * (32 * LDSH) + r * LDSH + kk;
            sWh[off] = wh[(size_t)r * H_ + k];
            sWl[off] = wl[(size_t)r * H_ + k];
        }
    }
    for (int i = tid; i < G_; i += 512) {
        sGhh[i] = __ldg(g_hh + (size_t)d * G_ + i);
        sBhh[i] = __ldg(b_hh + (size_t)d * G_ + i);
    }
    if (tid < H_) {
        sGho[tid] = __ldg(g_ho + (size_t)d * H_ + tid);
        sBho[tid] = __ldg(b_ho + (size_t)d * H_ + tid);
    }
    if (tid < H_) {
        hhi[(size_t)cta * H_ + tid] = __float2half_rn(0.f);
        hlo[(size_t)cta * H_ + tid] = __float2half_rn(0.f);
    }
    double c_reg = 0.0;
    grid_barrier();

    // staging map: part = hi/lo, each thread 2 uint4 loads per kb (kh0 + kh1)
    const int part = tid >> 8;                 // 0 = hi, 1 = lo
    const int idx = tid & 255;
    const int r_ = idx >> 2;                   // 0..63
    const int c8 = (idx & 3) * 8;              // 0,8,16,24
    const half_t* srcBase = (part == 0 ? hhi : hlo) + (size_t)(d * B_ + r_) * H_ + c8;

    for (int t = 0; t < S_; t++) {
        const int tt = (d == 0) ? t : (S_ - 1 - t);
        const float* gi = gih + (size_t)d * gihDir + (size_t)tt * gihTime + (size_t)cb * G_;
        float gir[4];
#pragma unroll
        for (int q = 0; q < 4; q++) gir[q] = __ldg(gi + tid + q * 512);

        // ======== GEMM phase ========
        wmma::fragment<wmma::accumulator, 16, 16, 16, float> accM, accX;
        wmma::fill_fragment(accM, 0.f);
        wmma::fill_fragment(accX, 0.f);

        uint4 p0 = __ldcg((const uint4*)(srcBase));            // kh0, kb=0
        uint4 p1 = __ldcg((const uint4*)(srcBase + 8 * 32));   // kh1, kb=0

#pragma unroll 2
        for (int kb = 0; kb < 8; kb++) {
            const int fb = kb & 1;
            {
                half_t* d0 = sA + ((fb * 2 + 0) * 2 + part) * SA_TILE + r_ * LDSH + c8;
                half_t* d1 = sA + ((fb * 2 + 1) * 2 + part) * SA_TILE + r_ * LDSH + c8;
                *(uint4*)d0 = p0;
                *(uint4*)d1 = p1;
            }
            __syncthreads();
            if (kb < 7) {
                int k0n = (kb + 1) * 32;
                p0 = __ldcg((const uint4*)(srcBase + k0n));
                p1 = __ldcg((const uint4*)(srcBase + k0n + 8 * 32));
            }
            const int kbg = kb + kh * 8;
            const half_t* bAh = sA + ((fb * 2 + kh) * 2 + 0) * SA_TILE + (wm * 16) * LDSH;
            const half_t* bAl = bAh + SA_TILE;
            const half_t* bWh = sWh + kbg * (32 * LDSH) + (wn * 16) * LDSH;
            const half_t* bWl = sWl + kbg * (32 * LDSH) + (wn * 16) * LDSH;
#pragma unroll
            for (int kk = 0; kk < 32; kk += 16) {
                wmma::fragment<wmma::matrix_a, 16, 16, 16, __half, wmma::row_major> ah, al;
                wmma::fragment<wmma::matrix_b, 16, 16, 16, __half, wmma::col_major> bh, bl;
                wmma::load_matrix_sync(ah, bAh + kk, LDSH);
                wmma::load_matrix_sync(al, bAl + kk, LDSH);
                wmma::load_matrix_sync(bh, bWh + kk, LDSH);
                wmma::load_matrix_sync(bl, bWl + kk, LDSH);
                wmma::mma_sync(accM, ah, bh, accM);
                wmma::mma_sync(accX, ah, bl, accX);
                wmma::mma_sync(accX, al, bh, accX);
            }
        }
        __syncthreads();   // staging dead; reuse as combine scratch
        if (kh == 1) {
            float* pc = sComb + (wt * 32 + lane) * 16;
#pragma unroll
            for (int e = 0; e < 8; e++) { pc[e] = accM.x[e]; pc[8 + e] = accX.x[e]; }
        }
        __syncthreads();
        if (kh == 0) {
            const float* pc = sComb + (wt * 32 + lane) * 16;
#pragma unroll
            for (int e = 0; e < 8; e++)
                accM.x[e] = (float)(((double)accM.x[e] + (double)pc[e])
                                    + ((double)accX.x[e] + (double)pc[8 + e]) * LO_INV);
            wmma::store_matrix_sync(Z + (size_t)(d * B_ + wm * 16) * G_ + n0 + wn * 16,
                                    accM, G_, wmma::mem_row_major);
        }

        grid_barrier();

        // ======== cell phase (row cta = (d, cb)); 1 elem/gate/thread ========
        {
            const float* z = Z + (size_t)cta * G_;
            float zr[4];
            float ps = 0.f;
#pragma unroll
            for (int q = 0; q < 4; q++) {
                zr[q] = __ldcg(z + tid + q * 512);
                ps += zr[q];
            }
            double s = block_reduce_d((double)ps, red);
            float mu = (float)(s / G_);
            float psq = 0.f;
#pragma unroll
            for (int q = 0; q < 4; q++) {
                float dv = zr[q] - mu;
                psq = fmaf(dv, dv, psq);
            }
            double sq = block_reduce_d((double)psq, red);
            float rstd = (float)rsqrt(sq / G_ + 1e-5);

            const int j = tid;
            float ai = fmaf((zr[0] - mu) * rstd, sGhh[j],            sBhh[j])            + gir[0];
            float af = fmaf((zr[1] - mu) * rstd, sGhh[j + H_],       sBhh[j + H_])       + gir[1];
            float ao = fmaf((zr[2] - mu) * rstd, sGhh[j + 2 * H_],   sBhh[j + 2 * H_])   + gir[2];
            float ag = fmaf((zr[3] - mu) * rstd, sGhh[j + 3 * H_],   sBhh[j + 3 * H_])   + gir[3];
            float ig = sigmoidf_(ai);
            float fg = sigmoidf_(af);
            float og = sigmoidf_(ao);
            float gg = tanhf(ag);
            double cn = (double)fg * c_reg + (double)(ig * gg);
            c_reg = cn;

            double s2 = block_reduce_d(cn, red);
            double muc = s2 / H_;
            double dvc = cn - muc;
            double sq2 = block_reduce_d(dvc * dvc, red);
            float rstdc = (float)rsqrt(sq2 / H_ + 1e-5);

            float lnc = fmaf((float)dvc * rstdc, sGho[j], sBho[j]);
            float hn = og * tanhf(lnc);
            size_t hi_ = (size_t)cta * H_ + j;
            __half hb = __float2half_rn(hn);
            hhi[hi_] = hb;
            hlo[hi_] = __float2half_rn((hn - __half2float(hb)) * LO_SCALE);
            if (writeOut && t == S_ - 1)
                out[(size_t)cb * (2 * H_) + (size_t)d * H_ + j] = hn;
        }
        grid_barrier();
    }
}

// ---------------- host orchestration ----------------
extern "C" void kernel_launch(void* const* d_in, const int* in_sizes, int n_in,
                              void* d_out, int out_size) {
    const float* x = (const float*)d_in[0];
    // d_in[1] = text_length (unused)
    const float* w_ih0 = (const float*)d_in[2];
    const float* w_hh0 = (const float*)d_in[3];
    const float* ln_ih0_g = (const float*)d_in[4];
    const float* ln_ih0_b = (const float*)d_in[5];
    const float* ln_hh0_g = (const float*)d_in[6];
    const float* ln_hh0_b = (const float*)d_in[7];
    const float* ln_ho0_g = (const float*)d_in[8];
    const float* ln_ho0_b = (const float*)d_in[9];
    const float* w_ih1 = (const float*)d_in[10];
    const float* w_hh1 = (const float*)d_in[11];
    const float* ln_ih1_g = (const float*)d_in[12];
    const float* ln_ih1_b = (const float*)d_in[13];
    const float* ln_hh1_g = (const float*)d_in[14];
    const float* ln_hh1_b = (const float*)d_in[15];
    const float* ln_ho1_g = (const float*)d_in[16];
    const float* ln_ho1_b = (const float*)d_in[17];
    float* out = (float*)d_out;

    float *G0, *G1, *Z;
    half_t *hhi, *hlo, *A0hi, *A0lo, *Wih0hi, *Wih0lo, *Whh0hi, *Whh0lo;
    half_t *Wih1hi, *Wih1lo, *Whh1hi, *Whh1lo, *XChi, *XClo;
    cudaGetSymbolAddress((void**)&G0, d_G0);
    cudaGetSymbolAddress((void**)&G1, d_G1);
    cudaGetSymbolAddress((void**)&Z, d_Zb);
    cudaGetSymbolAddress((void**)&hhi, d_hhi);
    cudaGetSymbolAddress((void**)&hlo, d_hlo);
    cudaGetSymbolAddress((void**)&A0hi, d_A0hi);
    cudaGetSymbolAddress((void**)&A0lo, d_A0lo);
    cudaGetSymbolAddress((void**)&Wih0hi, d_Wih0hi);
    cudaGetSymbolAddress((void**)&Wih0lo, d_Wih0lo);
    cudaGetSymbolAddress((void**)&Whh0hi, d_Whh0hi);
    cudaGetSymbolAddress((void**)&Whh0lo, d_Whh0lo);
    cudaGetSymbolAddress((void**)&Wih1hi, d_Wih1hi);
    cudaGetSymbolAddress((void**)&Wih1lo, d_Wih1lo);
    cudaGetSymbolAddress((void**)&Whh1hi, d_Whh1hi);
    cudaGetSymbolAddress((void**)&Whh1lo, d_Whh1lo);
    cudaGetSymbolAddress((void**)&XChi, d_XChi);
    cudaGetSymbolAddress((void**)&XClo, d_XClo);

    const int SCAN_SMEM = 28672 * 3 * 2 + (2048 * 2 + 512 * 2) * 4;  // 172032 + 20480 = 192512 B
    static int attr_set = 0;
    if (!attr_set) {
        cudaFuncSetAttribute(scan_kernel, cudaFuncAttributeMaxDynamicSharedMemorySize, SCAN_SMEM);
        attr_set = 1;
    }

    // 1) fused splits
    {
        int nx = S_ * B_ * E_ / 4;
        int n0 = 2 * G_ * E_ / 4, n1 = 2 * G_ * H_ / 4, n2 = 2 * G_ * 2 * H_ / 4, n3 = 2 * G_ * H_ / 4;
        int total = nx + n0 + n1 + n2 + n3;
        fused_split_kernel<<<(total + 255) / 256, 256>>>(
            x, A0hi, A0lo, nx,
            w_ih0, Wih0hi, Wih0lo, n0,
            w_hh0, Whh0hi, Whh0lo, n1,
            w_ih1, Wih1hi, Wih1lo, n2,
            w_hh1, Whh1hi, Whh1lo, n3);
    }

    // 2) layer-0 input projection
    {
        dim3 grid(G_ / 128, (S_ * B_) / 64, 2);
        gemm3_fp16_kernel<<<grid, 256>>>(A0hi, A0lo, Wih0hi, Wih0lo, G0,
                                         S_ * B_, G_, E_,
                                         0L, (long)G_ * E_, (long)S_ * B_ * G_);
    }
    // 3) LN
    ln_rows_kernel<<<2 * S_ * B_, 256>>>(G0, ln_ih0_g, ln_ih0_b, S_ * B_);

    // 4) layer-0 persistent scan
    scan_kernel<<<NCTA, 512, SCAN_SMEM>>>(Whh0hi, Whh0lo,
                                          G0, (long)B_ * G_, (long)S_ * B_ * G_,
                                          ln_hh0_g, ln_hh0_b, ln_ho0_g, ln_ho0_b,
                                          Z, hhi, hlo, 0, out);

    // 5) layer-1 input (constant over time due to aliasing bug)
    build_xc_kernel<<<(B_ * 2 * H_ + 255) / 256, 256>>>(hhi, hlo, XChi, XClo);
    {
        dim3 grid(G_ / 128, 1, 2);
        gemm3_fp16_kernel<<<grid, 256>>>(XChi, XClo, Wih1hi, Wih1lo, G1,
                                         B_, G_, 2 * H_,
                                         0L, (long)G_ * 2 * H_, (long)B_ * G_);
    }
    ln_rows_kernel<<<2 * B_, 256>>>(G1, ln_ih1_g, ln_ih1_b, B_);

    // 6) layer-1 persistent scan
    scan_kernel<<<NCTA, 512, SCAN_SMEM>>>(Whh1hi, Whh1lo,
                                          G1, 0L, (long)B_ * G_,
                                          ln_hh1_g, ln_hh1_b, ln_ho1_g, ln_ho1_b,
                                          Z, hhi, hlo, 1, out);
}

// round 16
// speedup vs baseline: 1.9006x; 1.6792x over previous
#include <cuda_runtime.h>
#include <cuda_fp16.h>
#include <cuda_bf16.h>
#include <mma.h>

using namespace nvcuda;

#define B_ 64
#define S_ 48
#define E_ 512
#define H_ 512
#define G_ 2048  /* 4H */
#define NCTA 128
#define LDSH 56            /* proj-gemm half stride */
#define LDW 520            /* scan W smem stride (halves) */
#define LDA 264            /* scan A smem stride (halves) */

typedef __half half_t;

// ---------------- scratch (static device memory; no allocations) ----------------
__device__ __align__(16) float d_G0[2 * S_ * B_ * G_];   // LN(x@Wih0^T), both dirs
__device__ __align__(16) float d_G1[2 * B_ * G_];        // LN(xc@Wih1^T)
__device__ __align__(16) float d_Zb[2 * B_ * G_];        // per-step h@Whh^T
// fp16 hi/lo pairs (lo pre-scaled by 2^11)
__device__ __align__(16) half_t d_hhi[2 * B_ * H_], d_hlo[2 * B_ * H_];
__device__ __align__(16) half_t d_A0hi[S_ * B_ * E_], d_A0lo[S_ * B_ * E_];
__device__ __align__(16) half_t d_Wih0hi[2 * G_ * E_], d_Wih0lo[2 * G_ * E_];
__device__ __align__(16) half_t d_Whh0hi[2 * G_ * H_], d_Whh0lo[2 * G_ * H_];
__device__ __align__(16) half_t d_Wih1hi[2 * G_ * 2 * H_], d_Wih1lo[2 * G_ * 2 * H_];
__device__ __align__(16) half_t d_Whh1hi[2 * G_ * H_], d_Whh1lo[2 * G_ * H_];
__device__ __align__(16) half_t d_XChi[B_ * 2 * H_], d_XClo[B_ * 2 * H_];

// sync state
__device__ unsigned d_bar_count = 0;
__device__ unsigned d_bar_gen = 0;
__device__ __align__(128) unsigned d_cntZ[2][32];   // per-direction monotonic arrival counters
__device__ __align__(128) unsigned d_cntH[2][32];

#define LO_SCALE 2048.0f
#define LO_INV (1.0 / 2048.0)

// ---------------- helpers ----------------
__device__ __forceinline__ double block_reduce_d(double a, double* buf) {
    const int tid = threadIdx.x;
    for (int o = 16; o > 0; o >>= 1)
        a += __shfl_down_sync(0xffffffffu, a, o);
    const int w = tid >> 5, lane = tid & 31;
    const int nw = blockDim.x >> 5;
    if (lane == 0) buf[w] = a;
    __syncthreads();
    if (w == 0) {
        double v = (lane < nw) ? buf[lane] : 0.0;
        for (int o = 8; o > 0; o >>= 1)
            v += __shfl_down_sync(0xffffffffu, v, o);
        if (lane == 0) buf[16] = v;
    }
    __syncthreads();
    return buf[16];
}

// fused (a, b) fp64 block reduction; buf >= 34 doubles
__device__ __forceinline__ double2 block_reduce_d2(double a, double b, double* buf) {
    const int tid = threadIdx.x;
    for (int o = 16; o > 0; o >>= 1) {
        a += __shfl_down_sync(0xffffffffu, a, o);
        b += __shfl_down_sync(0xffffffffu, b, o);
    }
    const int w = tid >> 5, lane = tid & 31;
    const int nw = blockDim.x >> 5;
    if (lane == 0) { buf[2 * w] = a; buf[2 * w + 1] = b; }
    __syncthreads();
    if (w == 0) {
        double va = (lane < nw) ? buf[2 * lane] : 0.0;
        double vb = (lane < nw) ? buf[2 * lane + 1] : 0.0;
        for (int o = 8; o > 0; o >>= 1) {
            va += __shfl_down_sync(0xffffffffu, va, o);
            vb += __shfl_down_sync(0xffffffffu, vb, o);
        }
        if (lane == 0) { buf[32] = va; buf[33] = vb; }
    }
    __syncthreads();
    double2 r; r.x = buf[32]; r.y = buf[33];
    return r;
}

__device__ __forceinline__ float sigmoidf_(float x) { return 1.f / (1.f + expf(-x)); }

// full-grid barrier (used once at scan init)
__device__ __forceinline__ void grid_barrier() {
    __syncthreads();
    if (threadIdx.x == 0) {
        __threadfence();
        unsigned gen = *((volatile unsigned*)&d_bar_gen);
        unsigned old = atomicAdd(&d_bar_count, 1u);
        if (old == NCTA - 1) {
            d_bar_count = 0;
            __threadfence();
            atomicAdd(&d_bar_gen, 1u);
        } else {
            while (*((volatile unsigned*)&d_bar_gen) == gen) { }
        }
    }
    __syncthreads();
}

// mma.sync m16n8k16 fp16 -> fp32
__device__ __forceinline__ void mma16816(float* dd,
                                         unsigned a0, unsigned a1, unsigned a2, unsigned a3,
                                         unsigned b0, unsigned b1) {
    asm volatile("mma.sync.aligned.m16n8k16.row.col.f32.f16.f16.f32 "
                 "{%0,%1,%2,%3}, {%4,%5,%6,%7}, {%8,%9}, {%0,%1,%2,%3};"
                 : "+f"(dd[0]), "+f"(dd[1]), "+f"(dd[2]), "+f"(dd[3])
                 : "r"(a0), "r"(a1), "r"(a2), "r"(a3), "r"(b0), "r"(b1));
}

// ---------------- fp16 hi/lo split (lo scaled by 2^11) ----------------
__device__ __forceinline__ unsigned pack2(__half a, __half b) {
    __half2 t = __halves2half2(a, b);
    return *reinterpret_cast<unsigned*>(&t);
}

__device__ __forceinline__ void split4h(float4 v, uint2& h, uint2& l) {
    __half hx = __float2half_rn(v.x), hy = __float2half_rn(v.y);
    __half hz = __float2half_rn(v.z), hw = __float2half_rn(v.w);
    __half lx = __float2half_rn((v.x - __half2float(hx)) * LO_SCALE);
    __half ly = __float2half_rn((v.y - __half2float(hy)) * LO_SCALE);
    __half lz = __float2half_rn((v.z - __half2float(hz)) * LO_SCALE);
    __half lw = __float2half_rn((v.w - __half2float(hw)) * LO_SCALE);
    h.x = pack2(hx, hy); h.y = pack2(hz, hw);
    l.x = pack2(lx, ly); l.y = pack2(lz, lw);
}

__global__ void fused_split_kernel(const float* __restrict__ x, half_t* __restrict__ xhi, half_t* __restrict__ xlo, int nx,
                                   const float* __restrict__ s0, half_t* __restrict__ h0, half_t* __restrict__ l0, int n0,
                                   const float* __restrict__ s1, half_t* __restrict__ h1, half_t* __restrict__ l1, int n1,
                                   const float* __restrict__ s2, half_t* __restrict__ h2, half_t* __restrict__ l2, int n2,
                                   const float* __restrict__ s3, half_t* __restrict__ h3, half_t* __restrict__ l3, int n3) {
    int i = blockIdx.x * blockDim.x + threadIdx.x;  // float4 index
    if (i < nx) {
        int e4 = i % (E_ / 4);
        int r = i / (E_ / 4);
        int s = r / B_;
        int b = r % B_;
        float4 v = *(const float4*)(x + ((size_t)b * S_ + s) * E_ + e4 * 4);
        uint2 hv, lv;
        split4h(v, hv, lv);
        ((uint2*)xhi)[i] = hv;
        ((uint2*)xlo)[i] = lv;
        return;
    }
    i -= nx;
    const float* s; half_t* h; half_t* l;
    if (i < n0) { s = s0; h = h0; l = l0; }
    else if ((i -= n0) < n1) { s = s1; h = h1; l = l1; }
    else if ((i -= n1) < n2) { s = s2; h = h2; l = l2; }
    else if ((i -= n2) < n3) { s = s3; h = h3; l = l3; }
    else return;
    float4 v = ((const float4*)s)[i];
    uint2 hv, lv;
    split4h(v, hv, lv);
    ((uint2*)h)[i] = hv;
    ((uint2*)l)[i] = lv;
}

// xc[b][k] = concat(h_dir0[b], h_dir1[b]) fp16 hi/lo
__global__ void build_xc_kernel(const half_t* __restrict__ hhi, const half_t* __restrict__ hlo,
                                half_t* __restrict__ xchi, half_t* __restrict__ xclo) {
    int i = blockIdx.x * blockDim.x + threadIdx.x;
    if (i < B_ * 2 * H_) {
        int k = i % (2 * H_);
        int b = i / (2 * H_);
        int d = k / H_;
        int j = k % H_;
        size_t src = (size_t)(d * B_ + b) * H_ + j;
        xchi[i] = hhi[src];
        xclo[i] = hlo[src];
    }
}

// ---------------- 3-term split-fp16 GEMM (input projections) ----------------
__global__ void __launch_bounds__(256, 1)
gemm3_fp16_kernel(const half_t* __restrict__ Ahi, const half_t* __restrict__ Alo,
                  const half_t* __restrict__ Whi, const half_t* __restrict__ Wlo,
                  float* __restrict__ C, int M, int N, int K,
                  long aBatch, long wBatch, long cBatch) {
    constexpr int BM = 64, BN = 128, BK = 32;
    const int z = blockIdx.z;
    Ahi += (size_t)z * aBatch; Alo += (size_t)z * aBatch;
    Whi += (size_t)z * wBatch; Wlo += (size_t)z * wBatch;
    C += (size_t)z * cBatch;
    const int m0 = blockIdx.y * BM, n0 = blockIdx.x * BN;
    const int tid = threadIdx.x;

    __shared__ __align__(16) half_t sAh[BM][LDSH];
    __shared__ __align__(16) half_t sAl[BM][LDSH];
    __shared__ __align__(16) half_t sBh[BN][LDSH];
    __shared__ __align__(16) half_t sBl[BN][LDSH];

    wmma::fragment<wmma::accumulator, 16, 16, 16, float> accM0[2][2], accM1[2][2], accX[2][2];
#pragma unroll
    for (int i = 0; i < 2; i++)
#pragma unroll
        for (int j = 0; j < 2; j++) {
            wmma::fill_fragment(accM0[i][j], 0.f);
            wmma::fill_fragment(accM1[i][j], 0.f);
            wmma::fill_fragment(accX[i][j], 0.f);
        }

    const int wid = tid >> 5;
    const int wm = wid >> 2;   // 0..1
    const int wn = wid & 3;    // 0..3
    const int Khalf = K >> 1;

    for (int k0 = 0; k0 < K; k0 += BK) {
#pragma unroll
        for (int i = tid; i < BM * 4; i += 256) {
            int r = i >> 2, q = i & 3;
            size_t g = (size_t)(m0 + r) * K + k0 + q * 8;
            *(uint4*)&sAh[r][q * 8] = *(const uint4*)(Ahi + g);
            *(uint4*)&sAl[r][q * 8] = *(const uint4*)(Alo + g);
        }
#pragma unroll
        for (int i = tid; i < BN * 4; i += 256) {
            int r = i >> 2, q = i & 3;
            size_t g = (size_t)(n0 + r) * K + k0 + q * 8;
            *(uint4*)&sBh[r][q * 8] = *(const uint4*)(Whi + g);
            *(uint4*)&sBl[r][q * 8] = *(const uint4*)(Wlo + g);
        }
        __syncthreads();
        const bool firstHalf = (k0 < Khalf);
#pragma unroll
        for (int kk = 0; kk < BK; kk += 16) {
            wmma::fragment<wmma::matrix_a, 16, 16, 16, __half, wmma::row_major> ah[2], al[2];
            wmma::fragment<wmma::matrix_b, 16, 16, 16, __half, wmma::col_major> bh[2], bl[2];
#pragma unroll
            for (int i = 0; i < 2; i++) {
                wmma::load_matrix_sync(ah[i], &sAh[wm * 32 + i * 16][kk], LDSH);
                wmma::load_matrix_sync(al[i], &sAl[wm * 32 + i * 16][kk], LDSH);
                wmma::load_matrix_sync(bh[i], &sBh[wn * 32 + i * 16][kk], LDSH);
                wmma::load_matrix_sync(bl[i], &sBl[wn * 32 + i * 16][kk], LDSH);
            }
            if (firstHalf) {
#pragma unroll
                for (int i = 0; i < 2; i++)
#pragma unroll
                    for (int j = 0; j < 2; j++)
                        wmma::mma_sync(accM0[i][j], ah[i], bh[j], accM0[i][j]);
            } else {
#pragma unroll
                for (int i = 0; i < 2; i++)
#pragma unroll
                    for (int j = 0; j < 2; j++)
                        wmma::mma_sync(accM1[i][j], ah[i], bh[j], accM1[i][j]);
            }
#pragma unroll
            for (int i = 0; i < 2; i++)
#pragma unroll
                for (int j = 0; j < 2; j++) {
                    wmma::mma_sync(accX[i][j], ah[i], bl[j], accX[i][j]);
                    wmma::mma_sync(accX[i][j], al[i], bh[j], accX[i][j]);
                }
        }
        __syncthreads();
    }
#pragma unroll
    for (int i = 0; i < 2; i++)
#pragma unroll
        for (int j = 0; j < 2; j++) {
#pragma unroll
            for (int e = 0; e < accM0[i][j].num_elements; e++)
                accM0[i][j].x[e] = (float)(((double)accM0[i][j].x[e] + (double)accM1[i][j].x[e])
                                           + (double)accX[i][j].x[e] * LO_INV);
            wmma::store_matrix_sync(&C[(size_t)(m0 + wm * 32 + i * 16) * N + n0 + wn * 32 + j * 16],
                                    accM0[i][j], N, wmma::mem_row_major);
        }
}

// ---------------- row LayerNorm: fp32 elementwise, fp64 cross-thread reductions ----------------
__global__ void ln_rows_kernel(float* __restrict__ data, const float* __restrict__ gamma,
                               const float* __restrict__ beta, int rowsPerDir) {
    __shared__ double red[20];
    const int width = G_;
    long row = blockIdx.x;
    int d = (int)(row / rowsPerDir);
    float* p = data + row * (long)width;
    const int tid = threadIdx.x;
    float v[8];
    float ps = 0.f;
#pragma unroll
    for (int q = 0; q < 8; q++) {
        v[q] = p[tid + q * 256];
        ps += v[q];
    }
    double s = block_reduce_d((double)ps, red);
    float mu = (float)(s / width);
    float psq = 0.f;
#pragma unroll
    for (int q = 0; q < 8; q++) {
        float dv = v[q] - mu;
        psq = fmaf(dv, dv, psq);
    }
    double sq = block_reduce_d((double)psq, red);
    float rstd = (float)rsqrt(sq / width + 1e-5);
    const float* g = gamma + (size_t)d * width;
    const float* be = beta + (size_t)d * width;
#pragma unroll
    for (int q = 0; q < 8; q++) {
        int j = tid + q * 256;
        p[j] = fmaf((v[q] - mu) * rstd, g[j], be[j]);
    }
}

// ================= persistent scan kernel =================
// 128 CTAs x 512 threads. GEMM: 16 warps, each m16 x n8 over full K via mma.sync.
// A staged in 2 K-chunks of 256; W resident. Dir-decoupled monotonic counters for sync.
__global__ void __launch_bounds__(512, 1)
scan_kernel(const half_t* __restrict__ Whh_hi, const half_t* __restrict__ Whh_lo,
            const float* __restrict__ gih, long gihTime, long gihDir,
            const float* __restrict__ g_hh, const float* __restrict__ b_hh,
            const float* __restrict__ g_ho, const float* __restrict__ b_ho,
            float* __restrict__ Z, half_t* __restrict__ hhi, half_t* __restrict__ hlo,
            int writeOut, float* __restrict__ out) {
    extern __shared__ half_t smh[];
    half_t* sWh = smh;                       // 32*520 = 16640 halves
    half_t* sWl = sWh + 32 * LDW;            // 16640
    half_t* sAh = sWl + 32 * LDW;            // 64*264 = 16896
    half_t* sAl = sAh + 64 * LDA;            // 16896
    float* sGhh = (float*)(sAl + 64 * LDA);  // 2048 floats
    float* sBhh = sGhh + 2048;
    float* sGho = sBhh + 2048;
    float* sBho = sGho + 512;
    __shared__ double red[34];

    const int tid = threadIdx.x;
    const int cta = blockIdx.x;
    const int d = cta >> 6;                  // direction
    const int n0 = (cta & 63) * 32;          // gemm column block
    const int cb = cta & 63;                 // cell batch row
    const int wid = tid >> 5;
    const int lane = tid & 31;
    const int wm = wid >> 2;                 // 0..3 (m16 slice)
    const int wn = wid & 3;                  // 0..3 (n8 slice)
    const int r4 = lane >> 2;                // groupID
    const int t2 = (lane & 3) * 2;           // threadID*2

    // ---- one-time fills ----
    {
        const half_t* wh = Whh_hi + ((size_t)d * G_ + n0) * H_;
        const half_t* wl = Whh_lo + ((size_t)d * G_ + n0) * H_;
        for (int i = tid; i < 32 * H_; i += 512) {
            int n = i >> 9, k = i & 511;
            sWh[n * LDW + k] = wh[(size_t)n * H_ + k];
            sWl[n * LDW + k] = wl[(size_t)n * H_ + k];
        }
    }
    for (int i = tid; i < G_; i += 512) {
        sGhh[i] = __ldg(g_hh + (size_t)d * G_ + i);
        sBhh[i] = __ldg(b_hh + (size_t)d * G_ + i);
    }
    if (tid < H_) {
        sGho[tid] = __ldg(g_ho + (size_t)d * H_ + tid);
        sBho[tid] = __ldg(b_ho + (size_t)d * H_ + tid);
        hhi[(size_t)cta * H_ + tid] = __float2half_rn(0.f);
        hlo[(size_t)cta * H_ + tid] = __float2half_rn(0.f);
    }
    if (cta == 0 && tid == 0) {
        d_cntZ[0][0] = 0; d_cntZ[1][0] = 0;
        d_cntH[0][0] = 0; d_cntH[1][0] = 0;
    }
    double c_reg = 0.0;
    grid_barrier();

    for (int t = 0; t < S_; t++) {
        // prefetch gi (independent of h)
        const int tt = (d == 0) ? t : (S_ - 1 - t);
        const float* gi = gih + (size_t)d * gihDir + (size_t)tt * gihTime + (size_t)cb * G_;
        float gir[4];
#pragma unroll
        for (int q = 0; q < 4; q++) gir[q] = __ldg(gi + tid + q * 512);

        // wait: this direction's h for step t is ready
        if (tid == 0) {
            while (*(volatile unsigned*)&d_cntH[d][0] < 64u * (unsigned)t) { }
        }
        __syncthreads();

        // ======== GEMM: Z[d][64][n0:n0+32] = h @ W^T (3-term fp16) ========
        float Da[4] = {0.f, 0.f, 0.f, 0.f};
        float Db[4] = {0.f, 0.f, 0.f, 0.f};
        float Xc[4] = {0.f, 0.f, 0.f, 0.f};

#pragma unroll
        for (int ck = 0; ck < 2; ck++) {
            // stage A chunk [64][256] hi+lo
#pragma unroll
            for (int j = 0; j < 4; j++) {
                int idx = tid + j * 512;           // 0..2047
                int rr = idx >> 5;                 // row
                int uu = idx & 31;                 // uint4 within row
                size_t gsrc = (size_t)(d * B_ + rr) * H_ + ck * 256 + uu * 8;
                *(uint4*)&sAh[rr * LDA + uu * 8] = __ldcg((const uint4*)(hhi + gsrc));
                *(uint4*)&sAl[rr * LDA + uu * 8] = __ldcg((const uint4*)(hlo + gsrc));
            }
            __syncthreads();
            const half_t* aBh = sAh + (wm * 16 + r4) * LDA;
            const half_t* aBl = sAl + (wm * 16 + r4) * LDA;
            const half_t* wBh = sWh + (wn * 8 + r4) * LDW + ck * 256;
            const half_t* wBl = sWl + (wn * 8 + r4) * LDW + ck * 256;
            float* Dm = ck ? Db : Da;
#pragma unroll
            for (int kc = 0; kc < 16; kc++) {
                const int c = kc * 16 + t2;
                unsigned ah0 = *(const unsigned*)(aBh + c);
                unsigned ah1 = *(const unsigned*)(aBh + 8 * LDA + c);
                unsigned ah2 = *(const unsigned*)(aBh + c + 8);
                unsigned ah3 = *(const unsigned*)(aBh + 8 * LDA + c + 8);
                unsigned al0 = *(const unsigned*)(aBl + c);
                unsigned al1 = *(const unsigned*)(aBl + 8 * LDA + c);
                unsigned al2 = *(const unsigned*)(aBl + c + 8);
                unsigned al3 = *(const unsigned*)(aBl + 8 * LDA + c + 8);
                unsigned bh0 = *(const unsigned*)(wBh + c);
                unsigned bh1 = *(const unsigned*)(wBh + c + 8);
                unsigned bl0 = *(const unsigned*)(wBl + c);
                unsigned bl1 = *(const unsigned*)(wBl + c + 8);
                mma16816(Dm, ah0, ah1, ah2, ah3, bh0, bh1);
                mma16816(Xc, ah0, ah1, ah2, ah3, bl0, bl1);
                mma16816(Xc, al0, al1, al2, al3, bh0, bh1);
            }
            __syncthreads();
        }
        // combine in fp64 and store Z tile
        {
            float f0 = (float)(((double)Da[0] + (double)Db[0]) + (double)Xc[0] * LO_INV);
            float f1 = (float)(((double)Da[1] + (double)Db[1]) + (double)Xc[1] * LO_INV);
            float f2 = (float)(((double)Da[2] + (double)Db[2]) + (double)Xc[2] * LO_INV);
            float f3 = (float)(((double)Da[3] + (double)Db[3]) + (double)Xc[3] * LO_INV);
            size_t zoff = (size_t)(d * B_ + wm * 16 + r4) * G_ + n0 + wn * 8 + t2;
            float2 v0; v0.x = f0; v0.y = f1;
            float2 v1; v1.x = f2; v1.y = f3;
            *(float2*)&Z[zoff] = v0;
            *(float2*)&Z[zoff + 8 * G_] = v1;
        }
        __syncthreads();
        if (tid == 0) {
            __threadfence();
            atomicAdd(&d_cntZ[d][0], 1u);
            // wait: all 64 column-CTAs of this dir have published Z for step t
            while (*(volatile unsigned*)&d_cntZ[d][0] < 64u * (unsigned)(t + 1)) { }
        }
        __syncthreads();

        // ======== cell (row cta = (d, cb)); fused one-pass fp64 LN stats ========
        {
            const float* z = Z + (size_t)cta * G_;
            float zr[4];
            float ps = 0.f, psq = 0.f;
#pragma unroll
            for (int q = 0; q < 4; q++) {
                zr[q] = __ldcg(z + tid + q * 512);
                ps += zr[q];
                psq = fmaf(zr[q], zr[q], psq);
            }
            double2 st = block_reduce_d2((double)ps, (double)psq, red);
            double mu_d = st.x / G_;
            double var = fmax(st.y / G_ - mu_d * mu_d, 0.0);
            float rstd = (float)rsqrt(var + 1e-5);
            float mu = (float)mu_d;

            const int j = tid;
            float ai = fmaf((zr[0] - mu) * rstd, sGhh[j],          sBhh[j])          + gir[0];
            float af = fmaf((zr[1] - mu) * rstd, sGhh[j + H_],     sBhh[j + H_])     + gir[1];
            float ao = fmaf((zr[2] - mu) * rstd, sGhh[j + 2 * H_], sBhh[j + 2 * H_]) + gir[2];
            float ag = fmaf((zr[3] - mu) * rstd, sGhh[j + 3 * H_], sBhh[j + 3 * H_]) + gir[3];
            float ig = sigmoidf_(ai);
            float fg = sigmoidf_(af);
            float og = sigmoidf_(ao);
            float gg = tanhf(ag);
            double cn = (double)fg * c_reg + (double)(ig * gg);
            c_reg = cn;

            double2 st2 = block_reduce_d2(cn, cn * cn, red);
            double muc = st2.x / H_;
            double varc = fmax(st2.y / H_ - muc * muc, 0.0);
            float rstdc = (float)rsqrt(varc + 1e-5);

            float dvf = (float)(cn - muc);
            float lnc = fmaf(dvf * rstdc, sGho[j], sBho[j]);
            float hn = og * tanhf(lnc);
            size_t hi_ = (size_t)cta * H_ + j;
            __half hb = __float2half_rn(hn);
            hhi[hi_] = hb;
            hlo[hi_] = __float2half_rn((hn - __half2float(hb)) * LO_SCALE);
            if (writeOut && t == S_ - 1)
                out[(size_t)cb * (2 * H_) + (size_t)d * H_ + j] = hn;
        }
        __syncthreads();
        if (tid == 0) {
            __threadfence();
            atomicAdd(&d_cntH[d][0], 1u);
        }
    }
}

// ---------------- host orchestration ----------------
extern "C" void kernel_launch(void* const* d_in, const int* in_sizes, int n_in,
                              void* d_out, int out_size) {
    const float* x = (const float*)d_in[0];
    // d_in[1] = text_length (unused)
    const float* w_ih0 = (const float*)d_in[2];
    const float* w_hh0 = (const float*)d_in[3];
    const float* ln_ih0_g = (const float*)d_in[4];
    const float* ln_ih0_b = (const float*)d_in[5];
    const float* ln_hh0_g = (const float*)d_in[6];
    const float* ln_hh0_b = (const float*)d_in[7];
    const float* ln_ho0_g = (const float*)d_in[8];
    const float* ln_ho0_b = (const float*)d_in[9];
    const float* w_ih1 = (const float*)d_in[10];
    const float* w_hh1 = (const float*)d_in[11];
    const float* ln_ih1_g = (const float*)d_in[12];
    const float* ln_ih1_b = (const float*)d_in[13];
    const float* ln_hh1_g = (const float*)d_in[14];
    const float* ln_hh1_b = (const float*)d_in[15];
    const float* ln_ho1_g = (const float*)d_in[16];
    const float* ln_ho1_b = (const float*)d_in[17];
    float* out = (float*)d_out;

    float *G0, *G1, *Z;
    half_t *hhi, *hlo, *A0hi, *A0lo, *Wih0hi, *Wih0lo, *Whh0hi, *Whh0lo;
    half_t *Wih1hi, *Wih1lo, *Whh1hi, *Whh1lo, *XChi, *XClo;
    cudaGetSymbolAddress((void**)&G0, d_G0);
    cudaGetSymbolAddress((void**)&G1, d_G1);
    cudaGetSymbolAddress((void**)&Z, d_Zb);
    cudaGetSymbolAddress((void**)&hhi, d_hhi);
    cudaGetSymbolAddress((void**)&hlo, d_hlo);
    cudaGetSymbolAddress((void**)&A0hi, d_A0hi);
    cudaGetSymbolAddress((void**)&A0lo, d_A0lo);
    cudaGetSymbolAddress((void**)&Wih0hi, d_Wih0hi);
    cudaGetSymbolAddress((void**)&Wih0lo, d_Wih0lo);
    cudaGetSymbolAddress((void**)&Whh0hi, d_Whh0hi);
    cudaGetSymbolAddress((void**)&Whh0lo, d_Whh0lo);
    cudaGetSymbolAddress((void**)&Wih1hi, d_Wih1hi);
    cudaGetSymbolAddress((void**)&Wih1lo, d_Wih1lo);
    cudaGetSymbolAddress((void**)&Whh1hi, d_Whh1hi);
    cudaGetSymbolAddress((void**)&Whh1lo, d_Whh1lo);
    cudaGetSymbolAddress((void**)&XChi, d_XChi);
    cudaGetSymbolAddress((void**)&XClo, d_XClo);

    // smem: W (2*16640) + A (2*16896) halves + params (5120 floats)
    const int SCAN_SMEM = (2 * 32 * LDW + 2 * 64 * LDA) * 2 + (2048 * 2 + 512 * 2) * 4;  // 154624 B
    static int attr_set = 0;
    if (!attr_set) {
        cudaFuncSetAttribute(scan_kernel, cudaFuncAttributeMaxDynamicSharedMemorySize, SCAN_SMEM);
        attr_set = 1;
    }

    // 1) fused splits
    {
        int nx = S_ * B_ * E_ / 4;
        int n0 = 2 * G_ * E_ / 4, n1 = 2 * G_ * H_ / 4, n2 = 2 * G_ * 2 * H_ / 4, n3 = 2 * G_ * H_ / 4;
        int total = nx + n0 + n1 + n2 + n3;
        fused_split_kernel<<<(total + 255) / 256, 256>>>(
            x, A0hi, A0lo, nx,
            w_ih0, Wih0hi, Wih0lo, n0,
            w_hh0, Whh0hi, Whh0lo, n1,
            w_ih1, Wih1hi, Wih1lo, n2,
            w_hh1, Whh1hi, Whh1lo, n3);
    }

    // 2) layer-0 input projection
    {
        dim3 grid(G_ / 128, (S_ * B_) / 64, 2);
        gemm3_fp16_kernel<<<grid, 256>>>(A0hi, A0lo, Wih0hi, Wih0lo, G0,
                                         S_ * B_, G_, E_,
                                         0L, (long)G_ * E_, (long)S_ * B_ * G_);
    }
    // 3) LN
    ln_rows_kernel<<<2 * S_ * B_, 256>>>(G0, ln_ih0_g, ln_ih0_b, S_ * B_);

    // 4) layer-0 persistent scan
    scan_kernel<<<NCTA, 512, SCAN_SMEM>>>(Whh0hi, Whh0lo,
                                          G0, (long)B_ * G_, (long)S_ * B_ * G_,
                                          ln_hh0_g, ln_hh0_b, ln_ho0_g, ln_ho0_b,
                                          Z, hhi, hlo, 0, out);

    // 5) layer-1 input (constant over time due to aliasing bug)
    build_xc_kernel<<<(B_ * 2 * H_ + 255) / 256, 256>>>(hhi, hlo, XChi, XClo);
    {
        dim3 grid(G_ / 128, 1, 2);
        gemm3_fp16_kernel<<<grid, 256>>>(XChi, XClo, Wih1hi, Wih1lo, G1,
                                         B_, G_, 2 * H_,
                                         0L, (long)G_ * 2 * H_, (long)B_ * G_);
    }
    ln_rows_kernel<<<2 * B_, 256>>>(G1, ln_ih1_g, ln_ih1_b, B_);

    // 6) layer-1 persistent scan
    scan_kernel<<<NCTA, 512, SCAN_SMEM>>>(Whh1hi, Whh1lo,
                                          G1, 0L, (long)B_ * G_,
                                          ln_hh1_g, ln_hh1_b, ln_ho1_g, ln_ho1_b,
                                          Z, hhi, hlo, 1, out);
}